// round 17
// baseline (speedup 1.0000x reference)
#include <cuda_runtime.h>
#include <cuda_fp16.h>
#include <mma.h>
#include <math.h>
#include <float.h>

using namespace nvcuda;

#define NN 50000
#define EE 800000
#define ET (EE + NN)
#define SCAN_B 49   // ceil(50000/1024)

#define SA_LD 136
#define SW_LD 136
#define SC_LD 132
#define GEMM_SMEM (64 * SA_LD * 2 + 128 * SW_LD * 2)   // 52224 B

// ---------------- scratch ---------------------------------------------------
__device__ __half g_h1[NN * 128];
__device__ __half g_h2[NN * 128];
__device__ float  g_agg1[NN * 128];
__device__ float  g_as1[NN * 4];
__device__ float  g_ad1[NN * 4];
__device__ float  g_as2[NN];
__device__ float  g_ad2[NN];
__device__ int    g_deg[NN];           // zero at load; re-zeroed by k_scan_part
__device__ int    g_scan[SCAN_B * 1024];
__device__ int    g_scan2[SCAN_B * 1024];
__device__ int    g_bsum[SCAN_B];
__device__ int    g_rowptr[NN + 1];
__device__ int    g_fill[NN];
__device__ int2   g_cd[ET];            // packed (src, dst), CSR order
__device__ float  g_w1[4 * ET];        // exp weights, HEAD-MAJOR, CSR order
__device__ float  g_w2[ET];            // layer2, CSR order

__device__ __forceinline__ float lrelu(float x) { return x > 0.f ? x : 0.2f * x; }
__device__ __forceinline__ float elu(float x)   { return x > 0.f ? x : expm1f(x); }

// ---------------- CSR build -------------------------------------------------
__global__ void k_count(const int* __restrict__ ei) {
    int e = blockIdx.x * blockDim.x + threadIdx.x;
    if (e >= ET) return;
    int d = (e < EE) ? ei[EE + e] : (e - EE);
    atomicAdd(&g_deg[d], 1);
}

__global__ void k_scan_part() {
    __shared__ int sh[1024];
    int tid = threadIdx.x;
    int i = blockIdx.x * 1024 + tid;
    int v = (i < NN) ? g_deg[i] : 0;
    sh[tid] = v;
    __syncthreads();
#pragma unroll
    for (int off = 1; off < 1024; off <<= 1) {
        int t = (tid >= off) ? sh[tid - off] : 0;
        __syncthreads();
        sh[tid] += t;
        __syncthreads();
    }
    g_scan[i]  = sh[tid];
    g_scan2[i] = sh[tid] - v;
    if (i < NN) g_deg[i] = 0;
    if (tid == 1023) g_bsum[blockIdx.x] = sh[tid];
}

__global__ void k_rowptr() {
    __shared__ int sb[SCAN_B + 1];
    int t = threadIdx.x;
    if (t < SCAN_B) sb[t + 1] = g_bsum[t];
    __syncthreads();
    if (t == 0) {
        sb[0] = 0;
        for (int b = 1; b < SCAN_B; b++) sb[b] += sb[b - 1];
    }
    __syncthreads();
    int i = blockIdx.x * blockDim.x + t;
    if (i >= NN) return;
    int boff = sb[i >> 10];
    g_rowptr[i + 1] = g_scan[i] + boff;
    g_fill[i] = g_scan2[i] + boff;
    if (i == 0) g_rowptr[0] = 0;
}

// fill a sub-range of edges [lo, hi) — two instances run on two streams
__global__ void k_fill(const int* __restrict__ ei, int lo, int hi) {
    int e = lo + blockIdx.x * blockDim.x + threadIdx.x;
    if (e >= hi) return;
    int s, d;
    if (e < EE) { s = ei[e]; d = ei[EE + e]; } else { s = e - EE; d = s; }
    int pos = atomicAdd(&g_fill[d], 1);
    g_cd[pos] = make_int2(s, d);
}

// ---------------- tensor-core GEMM [NN,128]@[128,128], padded smem ----------
template <int LAYER>
__global__ void __launch_bounds__(512) k_gemm_tc(const float* __restrict__ Xext,
                                                 const float* __restrict__ W,
                                                 const float* __restrict__ asrc,
                                                 const float* __restrict__ adst) {
    extern __shared__ __align__(16) char smem[];
    __half* sA = (__half*)smem;
    __half* sW = (__half*)(smem + 64 * SA_LD * 2);
    float*  sC = (float*)smem;

    const float* __restrict__ X = (LAYER == 0) ? Xext : g_agg1;
    __half* __restrict__ H = (LAYER == 0) ? g_h1 : g_h2;

    int tid = threadIdx.x;
    int row0 = blockIdx.x * 64;

#pragma unroll
    for (int j = 0; j < 8; j++) {
        int idx = tid + j * 512;
        int r = idx >> 5, c4 = idx & 31;
        float4 v = ((const float4*)W)[idx];
        __half2 h0 = __floats2half2_rn(v.x, v.y);
        __half2 h1 = __floats2half2_rn(v.z, v.w);
        *(__half2*)(sW + r * SW_LD + c4 * 4)     = h0;
        *(__half2*)(sW + r * SW_LD + c4 * 4 + 2) = h1;
    }
#pragma unroll
    for (int j = 0; j < 4; j++) {
        int idx = tid + j * 512;
        int r = idx >> 5, c4 = idx & 31;
        int row = row0 + r;
        float4 v = make_float4(0.f, 0.f, 0.f, 0.f);
        if (row < NN) v = ((const float4*)X)[row * 32 + c4];
        __half2 h0 = __floats2half2_rn(v.x, v.y);
        __half2 h1 = __floats2half2_rn(v.z, v.w);
        *(__half2*)(sA + r * SA_LD + c4 * 4)     = h0;
        *(__half2*)(sA + r * SA_LD + c4 * 4 + 2) = h1;
    }
    __syncthreads();

    int wid = tid >> 5;
    int wr = wid >> 2, wc = wid & 3;

    wmma::fragment<wmma::accumulator, 16, 16, 16, float> c0, c1;
    wmma::fill_fragment(c0, 0.f);
    wmma::fill_fragment(c1, 0.f);

#pragma unroll
    for (int k = 0; k < 8; k++) {
        wmma::fragment<wmma::matrix_a, 16, 16, 16, __half, wmma::row_major> af;
        wmma::fragment<wmma::matrix_b, 16, 16, 16, __half, wmma::row_major> bf0, bf1;
        wmma::load_matrix_sync(af, sA + wr * 16 * SA_LD + k * 16, SA_LD);
        wmma::load_matrix_sync(bf0, sW + k * 16 * SW_LD + wc * 32, SW_LD);
        wmma::load_matrix_sync(bf1, sW + k * 16 * SW_LD + wc * 32 + 16, SW_LD);
        wmma::mma_sync(c0, af, bf0, c0);
        wmma::mma_sync(c1, af, bf1, c1);
    }
    __syncthreads();

    wmma::store_matrix_sync(sC + wr * 16 * SC_LD + wc * 32,      c0, SC_LD, wmma::mem_row_major);
    wmma::store_matrix_sync(sC + wr * 16 * SC_LD + wc * 32 + 16, c1, SC_LD, wmma::mem_row_major);
    __syncthreads();

    {
        int r = tid >> 3;
        int t8 = tid & 7;
        int c0i = t8 * 16;
        int row = row0 + r;
        if (row < NN) {
            float v[16];
#pragma unroll
            for (int j = 0; j < 16; j++) v[j] = sC[r * SC_LD + c0i + j];

            __half2 hh[8];
#pragma unroll
            for (int j = 0; j < 8; j++) hh[j] = __floats2half2_rn(v[2 * j], v[2 * j + 1]);
            uint4 p0 = make_uint4(*(unsigned*)&hh[0], *(unsigned*)&hh[1], *(unsigned*)&hh[2], *(unsigned*)&hh[3]);
            uint4 p1 = make_uint4(*(unsigned*)&hh[4], *(unsigned*)&hh[5], *(unsigned*)&hh[6], *(unsigned*)&hh[7]);
            ((uint4*)H)[row * 16 + t8 * 2]     = p0;
            ((uint4*)H)[row * 16 + t8 * 2 + 1] = p1;

            float s = 0.f, d = 0.f;
#pragma unroll
            for (int j = 0; j < 16; j++) {
                s += v[j] * asrc[c0i + j];
                d += v[j] * adst[c0i + j];
            }
            if (LAYER == 0) {
                s += __shfl_xor_sync(0xffffffffu, s, 1);
                d += __shfl_xor_sync(0xffffffffu, d, 1);
                if ((t8 & 1) == 0) {
                    g_as1[row * 4 + (t8 >> 1)] = s;
                    g_ad1[row * 4 + (t8 >> 1)] = d;
                }
            } else {
#pragma unroll
                for (int off = 1; off < 8; off <<= 1) {
                    s += __shfl_xor_sync(0xffffffffu, s, off);
                    d += __shfl_xor_sync(0xffffffffu, d, off);
                }
                if (t8 == 0) { g_as2[row] = s; g_ad2[row] = d; }
            }
        }
    }
}

// ---------------- edge-parallel exp weights (CSR order, head-major) ---------
__global__ void k_edgew1() {
    int e = blockIdx.x * blockDim.x + threadIdx.x;
    if (e >= ET) return;
    int2 cd = g_cd[e];
    float4 a = ((const float4*)g_as1)[cd.x];
    float4 b = ((const float4*)g_ad1)[cd.y];
    g_w1[0 * ET + e] = __expf(lrelu(a.x + b.x));
    g_w1[1 * ET + e] = __expf(lrelu(a.y + b.y));
    g_w1[2 * ET + e] = __expf(lrelu(a.z + b.z));
    g_w1[3 * ET + e] = __expf(lrelu(a.w + b.w));
}

__global__ void k_edgew2() {
    int e = blockIdx.x * blockDim.x + threadIdx.x;
    if (e >= ET) return;
    int2 cd = g_cd[e];
    g_w2[e] = __expf(lrelu(g_as2[cd.x] + g_ad2[cd.y]));
}

// ---------------- node aggregation, layer 1 (4 heads), 8x unroll ------------
__global__ void k_node1(const float* __restrict__ b1) {
    int w = (blockIdx.x * blockDim.x + threadIdx.x) >> 5;
    int lane = threadIdx.x & 31;
    if (w >= NN) return;
    int beg = g_rowptr[w], end = g_rowptr[w + 1];
    const float* __restrict__ wh_base = g_w1 + (lane >> 3) * ET;

    float ws = 0.f;
    float4 acc = make_float4(0.f, 0.f, 0.f, 0.f);

    int i = beg;
    for (; i + 8 <= end; i += 8) {
        int   ss[8];
        float wv[8];
        uint2 rr[8];
#pragma unroll
        for (int j = 0; j < 8; j++) { ss[j] = g_cd[i + j].x; wv[j] = wh_base[i + j]; }
#pragma unroll
        for (int j = 0; j < 8; j++) rr[j] = ((const uint2*)g_h1)[ss[j] * 32 + lane];
#pragma unroll
        for (int j = 0; j < 8; j++) {
            ws += wv[j];
            float2 f01 = __half22float2(*reinterpret_cast<__half2*>(&rr[j].x));
            float2 f23 = __half22float2(*reinterpret_cast<__half2*>(&rr[j].y));
            acc.x += wv[j] * f01.x;
            acc.y += wv[j] * f01.y;
            acc.z += wv[j] * f23.x;
            acc.w += wv[j] * f23.y;
        }
    }
    for (; i + 4 <= end; i += 4) {
        int   ss[4];
        float wv[4];
        uint2 rr[4];
#pragma unroll
        for (int j = 0; j < 4; j++) { ss[j] = g_cd[i + j].x; wv[j] = wh_base[i + j]; }
#pragma unroll
        for (int j = 0; j < 4; j++) rr[j] = ((const uint2*)g_h1)[ss[j] * 32 + lane];
#pragma unroll
        for (int j = 0; j < 4; j++) {
            ws += wv[j];
            float2 f01 = __half22float2(*reinterpret_cast<__half2*>(&rr[j].x));
            float2 f23 = __half22float2(*reinterpret_cast<__half2*>(&rr[j].y));
            acc.x += wv[j] * f01.x;
            acc.y += wv[j] * f01.y;
            acc.z += wv[j] * f23.x;
            acc.w += wv[j] * f23.y;
        }
    }
    for (; i < end; i++) {
        int s = g_cd[i].x;
        float wh = wh_base[i];
        ws += wh;
        uint2 raw = ((const uint2*)g_h1)[s * 32 + lane];
        float2 f01 = __half22float2(*reinterpret_cast<__half2*>(&raw.x));
        float2 f23 = __half22float2(*reinterpret_cast<__half2*>(&raw.y));
        acc.x += wh * f01.x;
        acc.y += wh * f01.y;
        acc.z += wh * f23.x;
        acc.w += wh * f23.y;
    }

    float inv = 1.f / (ws + 1e-16f);
    float4 bv = ((const float4*)b1)[lane];
    float4 o;
    o.x = elu(acc.x * inv + bv.x);
    o.y = elu(acc.y * inv + bv.y);
    o.z = elu(acc.z * inv + bv.z);
    o.w = elu(acc.w * inv + bv.w);
    ((float4*)g_agg1)[w * 32 + lane] = o;
}

// ---------------- node aggregation, layer 2 (1 head), 8x unroll --------------
__global__ void k_node2(const float* __restrict__ b2, float* __restrict__ out) {
    int w = (blockIdx.x * blockDim.x + threadIdx.x) >> 5;
    int lane = threadIdx.x & 31;
    if (w >= NN) return;
    int beg = g_rowptr[w], end = g_rowptr[w + 1];

    float ws = 0.f;
    float4 acc = make_float4(0.f, 0.f, 0.f, 0.f);

    int i = beg;
    for (; i + 8 <= end; i += 8) {
        int   ss[8];
        float wv[8];
        uint2 rr[8];
#pragma unroll
        for (int j = 0; j < 8; j++) { ss[j] = g_cd[i + j].x; wv[j] = g_w2[i + j]; }
#pragma unroll
        for (int j = 0; j < 8; j++) rr[j] = ((const uint2*)g_h2)[ss[j] * 32 + lane];
#pragma unroll
        for (int j = 0; j < 8; j++) {
            ws += wv[j];
            float2 f01 = __half22float2(*reinterpret_cast<__half2*>(&rr[j].x));
            float2 f23 = __half22float2(*reinterpret_cast<__half2*>(&rr[j].y));
            acc.x += wv[j] * f01.x;
            acc.y += wv[j] * f01.y;
            acc.z += wv[j] * f23.x;
            acc.w += wv[j] * f23.y;
        }
    }
    for (; i + 4 <= end; i += 4) {
        int   ss[4];
        float wv[4];
        uint2 rr[4];
#pragma unroll
        for (int j = 0; j < 4; j++) { ss[j] = g_cd[i + j].x; wv[j] = g_w2[i + j]; }
#pragma unroll
        for (int j = 0; j < 4; j++) rr[j] = ((const uint2*)g_h2)[ss[j] * 32 + lane];
#pragma unroll
        for (int j = 0; j < 4; j++) {
            ws += wv[j];
            float2 f01 = __half22float2(*reinterpret_cast<__half2*>(&rr[j].x));
            float2 f23 = __half22float2(*reinterpret_cast<__half2*>(&rr[j].y));
            acc.x += wv[j] * f01.x;
            acc.y += wv[j] * f01.y;
            acc.z += wv[j] * f23.x;
            acc.w += wv[j] * f23.y;
        }
    }
    for (; i < end; i++) {
        int s = g_cd[i].x;
        float wv = g_w2[i];
        ws += wv;
        uint2 raw = ((const uint2*)g_h2)[s * 32 + lane];
        float2 f01 = __half22float2(*reinterpret_cast<__half2*>(&raw.x));
        float2 f23 = __half22float2(*reinterpret_cast<__half2*>(&raw.y));
        acc.x += wv * f01.x;
        acc.y += wv * f01.y;
        acc.z += wv * f23.x;
        acc.w += wv * f23.y;
    }

    float inv = 1.f / (ws + 1e-16f);
    float4 bv = ((const float4*)b2)[lane];
    float4 o;
    o.x = elu(acc.x * inv + bv.x);
    o.y = elu(acc.y * inv + bv.y);
    o.z = elu(acc.z * inv + bv.z);
    o.w = elu(acc.w * inv + bv.w);
    ((float4*)out)[w * 32 + lane] = o;
}

// ---------------- host launch ------------------------------------------------
extern "C" void kernel_launch(void* const* d_in, const int* in_sizes, int n_in,
                              void* d_out, int out_size) {
    const float* x    = (const float*)d_in[0];
    const int*   ei   = (const int*)  d_in[1];
    const float* W1   = (const float*)d_in[2];
    const float* a_s1 = (const float*)d_in[3];
    const float* a_d1 = (const float*)d_in[4];
    const float* b1   = (const float*)d_in[5];
    const float* W2   = (const float*)d_in[6];
    const float* a_s2 = (const float*)d_in[7];
    const float* a_d2 = (const float*)d_in[8];
    const float* b2   = (const float*)d_in[9];
    float* out = (float*)d_out;

    const int EB = (ET + 255) / 256;
    const int NB = (NN + 255) / 256;
    const int WARPB = (NN * 32 + 255) / 256;
    const int GB = (NN + 63) / 64;
    const int HALF = ET / 2;
    const int FB = (HALF + 255) / 256;
    const int FB2 = (ET - HALF + 255) / 256;

    cudaFuncSetAttribute(k_gemm_tc<0>, cudaFuncAttributeMaxDynamicSharedMemorySize, GEMM_SMEM);
    cudaFuncSetAttribute(k_gemm_tc<1>, cudaFuncAttributeMaxDynamicSharedMemorySize, GEMM_SMEM);

    cudaStream_t s1;
    cudaEvent_t evFork, evCsr, evJoin;
    cudaStreamCreateWithFlags(&s1, cudaStreamNonBlocking);
    cudaEventCreateWithFlags(&evFork, cudaEventDisableTiming);
    cudaEventCreateWithFlags(&evCsr,  cudaEventDisableTiming);
    cudaEventCreateWithFlags(&evJoin, cudaEventDisableTiming);

    cudaEventRecord(evFork, 0);
    cudaStreamWaitEvent(s1, evFork, 0);

    // leg A (s1): count -> scan -> rowptr -> fill half [0, HALF)
    k_count<<<EB, 256, 0, s1>>>(ei);
    k_scan_part<<<SCAN_B, 1024, 0, s1>>>();
    k_rowptr<<<NB, 256, 0, s1>>>();
    cudaEventRecord(evCsr, s1);
    k_fill<<<FB, 256, 0, s1>>>(ei, 0, HALF);
    cudaEventRecord(evJoin, s1);

    // leg B (default): GEMM1, then fill half [HALF, ET) once rowptr is ready
    k_gemm_tc<0><<<GB, 512, GEMM_SMEM>>>(x, W1, a_s1, a_d1);
    cudaStreamWaitEvent(0, evCsr, 0);
    k_fill<<<FB2, 256>>>(ei, HALF, ET);

    // join: both fill halves done
    cudaStreamWaitEvent(0, evJoin, 0);

    k_edgew1<<<EB, 256>>>();
    k_node1<<<WARPB, 256>>>(b1);

    k_gemm_tc<1><<<GB, 512, GEMM_SMEM>>>(nullptr, W2, a_s2, a_d2);
    k_edgew2<<<EB, 256>>>();
    k_node2<<<WARPB, 256>>>(b2, out);
}